// round 3
// baseline (speedup 1.0000x reference)
#include <cuda_runtime.h>
#include <cuda_bf16.h>

#define BS 16
#define NN 512
#define DD 256
#define RR 2
#define M_TOTAL (BS * NN)           // 8192
#define K_TOTAL (3 * DD)            // 768

// Scratch (no allocations allowed). 16B-aligned for float4 access.
__device__ __align__(16) unsigned char g_maskT[(size_t)BS * NN * NN]; // [b][j][i], bit0=punct, bit1=aug
__device__ __align__(16) float g_agg[(size_t)RR * BS * NN * DD];      // [r][b][j][d]
__device__ __align__(16) float g_h[(size_t)BS * NN * DD];             // layer-1 output

// ---------------------------------------------------------------------------
// Kernel 1: build packed transposed masks once.
// NOTE: the adjacency tensors are int32 on device (JAX downcasts int64 with
// x64 disabled). r=0 punct (punct==1 && aug!=1), r=1 aug (aug==1). Disjoint.
// Stored transposed as maskT[b][j][i] so aggregation reads a contiguous
// 512-byte row per target node j.
// ---------------------------------------------------------------------------
__global__ void build_masks_kernel(const int* __restrict__ aug,
                                   const int* __restrict__ punct) {
    __shared__ unsigned char tile[32][33];
    const int b  = blockIdx.z;
    const int i0 = blockIdx.y * 32;
    const int j0 = blockIdx.x * 32;
    const int tx = threadIdx.x;   // 32
    const int ty = threadIdx.y;   // 8
    const size_t base = (size_t)b * NN * NN;

    #pragma unroll
    for (int s = 0; s < 4; s++) {
        const int ii = ty + s * 8;
        const size_t idx = base + (size_t)(i0 + ii) * NN + (j0 + tx);
        const int a = aug[idx];
        const int p = punct[idx];
        tile[ii][tx] = (a == 1) ? (unsigned char)2
                                : ((p == 1) ? (unsigned char)1 : (unsigned char)0);
    }
    __syncthreads();
    #pragma unroll
    for (int s = 0; s < 4; s++) {
        const int jj = ty + s * 8;
        g_maskT[base + (size_t)(j0 + jj) * NN + (i0 + tx)] = tile[tx][jj];
    }
}

// ---------------------------------------------------------------------------
// Kernel 2: sparse mean-aggregation for both relations.
// Block = (j, b). 256 threads, one feature channel per thread.
// use_h != 0 -> read from g_h instead of x.
// ---------------------------------------------------------------------------
__global__ void aggregate_kernel(const float* __restrict__ x, int use_h) {
    const int j = blockIdx.x;
    const int b = blockIdx.y;
    const int t = threadIdx.x;   // 0..255 = feature channel d

    __shared__ unsigned char sm[NN];
    if (t < NN / 4) {
        ((unsigned int*)sm)[t] =
            ((const unsigned int*)(g_maskT + ((size_t)b * NN + j) * NN))[t];
    }
    __syncthreads();

    const float* __restrict__ src = use_h ? (const float*)g_h : x;
    const float* __restrict__ xb = src + (size_t)b * NN * DD;
    float acc0 = 0.f, acc1 = 0.f;
    int c0 = 0, c1 = 0;

    for (int i = 0; i < NN; i++) {
        const unsigned char m = sm[i];
        if (m) {
            const float v = xb[(size_t)i * DD + t];
            if (m & 1) { acc0 += v; c0++; }
            if (m & 2) { acc1 += v; c1++; }
        }
    }

    const size_t o = ((size_t)b * NN + j) * DD + t;
    g_agg[o]                        = acc0 * (1.0f / (float)max(c0, 1));
    g_agg[(size_t)BS * NN * DD + o] = acc1 * (1.0f / (float)max(c1, 1));
}

// ---------------------------------------------------------------------------
// Kernel 3: fused RGCN transform + bias + ELU as one GEMM:
//   out[m,e] = elu( [X | agg0 | agg1][m,:] @ [Wroot; Wrel0; Wrel1][:,e] + b[e] )
// M=8192, K=768, N=256.  64x64 block tile, 16 K-tile, 4x4 per thread.
// in_is_h: read activations from g_h;  out_is_h: write result to g_h.
// ---------------------------------------------------------------------------
__global__ void __launch_bounds__(256)
rgcn_gemm_kernel(const float* __restrict__ Xin, int in_is_h,
                 const float* __restrict__ Wroot,
                 const float* __restrict__ Wrel,   // [2][256][256]
                 const float* __restrict__ bias,
                 float* __restrict__ Oout, int out_is_h) {
    __shared__ alignas(16) float As[16][64];   // transposed: [k][m]
    __shared__ alignas(16) float Bs[16][64];   // [k][e]

    const float* __restrict__ X = in_is_h ? (const float*)g_h : Xin;
    float* __restrict__ out = out_is_h ? (float*)g_h : Oout;

    const int t  = threadIdx.x;
    const int tx = t & 15;         // e-tile lane
    const int ty = t >> 4;         // m-tile lane
    const int m0 = blockIdx.y * 64;
    const int e0 = blockIdx.x * 64;

    const int arow = t >> 2;       // A loader: row 0..63
    const int akq  = t & 3;        //           k-quad 0..3
    const int bk   = t >> 4;       // B loader: k row 0..15
    const int beq  = t & 15;       //           e-quad 0..15

    const float* A0 = g_agg;
    const float* A1 = g_agg + (size_t)BS * NN * DD;

    float acc[4][4] = {};

    for (int kt = 0; kt < K_TOTAL; kt += 16) {
        const int seg  = kt >> 8;          // 0: root/x, 1: rel0, 2: rel1
        const int ksub = kt & 255;
        const float* __restrict__ Asrc = (seg == 0) ? X : (seg == 1 ? A0 : A1);
        const float* __restrict__ Bsrc =
            (seg == 0) ? Wroot : (Wrel + (size_t)(seg - 1) * DD * DD);

        const float4 av = *(const float4*)&Asrc[(size_t)(m0 + arow) * DD + ksub + akq * 4];
        As[akq * 4 + 0][arow] = av.x;
        As[akq * 4 + 1][arow] = av.y;
        As[akq * 4 + 2][arow] = av.z;
        As[akq * 4 + 3][arow] = av.w;
        *(float4*)&Bs[bk][beq * 4] =
            *(const float4*)&Bsrc[(size_t)(ksub + bk) * DD + e0 + beq * 4];
        __syncthreads();

        #pragma unroll
        for (int kk = 0; kk < 16; kk++) {
            const float4 a4 = *(const float4*)&As[kk][ty * 4];
            const float4 b4 = *(const float4*)&Bs[kk][tx * 4];
            const float a[4]  = {a4.x, a4.y, a4.z, a4.w};
            const float bb[4] = {b4.x, b4.y, b4.z, b4.w};
            #pragma unroll
            for (int p = 0; p < 4; p++)
                #pragma unroll
                for (int q = 0; q < 4; q++)
                    acc[p][q] += a[p] * bb[q];
        }
        __syncthreads();
    }

    #pragma unroll
    for (int p = 0; p < 4; p++) {
        const int m = m0 + ty * 4 + p;
        #pragma unroll
        for (int q = 0; q < 4; q++) {
            const int e = e0 + tx * 4 + q;
            const float v = acc[p][q] + bias[e];
            out[(size_t)m * DD + e] = (v > 0.f) ? v : expm1f(v);
        }
    }
}

// ---------------------------------------------------------------------------
// Launch: masks once, then per layer: sparse agg -> fused GEMM+bias+ELU.
// ---------------------------------------------------------------------------
extern "C" void kernel_launch(void* const* d_in, const int* in_sizes, int n_in,
                              void* d_out, int out_size) {
    const float* x       = (const float*)d_in[0];
    const float* w_rel1  = (const float*)d_in[1];
    const float* w_root1 = (const float*)d_in[2];
    const float* b1      = (const float*)d_in[3];
    const float* w_rel2  = (const float*)d_in[4];
    const float* w_root2 = (const float*)d_in[5];
    const float* b2      = (const float*)d_in[6];
    const int* aug   = (const int*)d_in[7];
    const int* punct = (const int*)d_in[8];
    float* out = (float*)d_out;

    build_masks_kernel<<<dim3(NN / 32, NN / 32, BS), dim3(32, 8)>>>(aug, punct);

    // Layer 1: agg(x) -> h = elu(gemm)
    aggregate_kernel<<<dim3(NN, BS), 256>>>(x, 0);
    rgcn_gemm_kernel<<<dim3(DD / 64, M_TOTAL / 64), 256>>>(
        x, 0, w_root1, w_rel1, b1, nullptr, 1);

    // Layer 2: agg(h) -> out = elu(gemm)
    aggregate_kernel<<<dim3(NN, BS), 256>>>(nullptr, 1);
    rgcn_gemm_kernel<<<dim3(DD / 64, M_TOTAL / 64), 256>>>(
        nullptr, 1, w_root2, w_rel2, b2, out, 0);
}

// round 4
// speedup vs baseline: 3.5316x; 3.5316x over previous
#include <cuda_runtime.h>
#include <cuda_bf16.h>

#define BS 16
#define NN 512
#define DD 256
#define RR 2
#define M_TOTAL (BS * NN)           // 8192
#define K_TOTAL (3 * DD)            // 768

// Scratch (no allocations allowed).
__device__ __align__(16) unsigned char g_maskT[(size_t)BS * NN * NN];   // [b][j][i]
__device__ __align__(16) unsigned short g_list[(size_t)BS * NN * NN / 1]; // per (b,j): r0 from front, r1 from back (disjoint, <=512 total)
__device__ int   g_cnt[RR][BS * NN];
__device__ float g_inv[RR][BS * NN];
__device__ __align__(16) float g_agg[(size_t)RR * BS * NN * DD];        // [r][b][j][d]
__device__ __align__(16) float g_h[(size_t)BS * NN * DD];               // layer-1 output

// ---------------------------------------------------------------------------
// Kernel 1: build packed transposed masks (adjacency arrays are int32 on
// device — JAX downcasts int64). bit0 = punct edge (punct==1 && aug!=1),
// bit1 = aug edge (aug==1). Transposed so each target j owns a contiguous row.
// ---------------------------------------------------------------------------
__global__ void build_masks_kernel(const int* __restrict__ aug,
                                   const int* __restrict__ punct) {
    __shared__ unsigned char tile[32][33];
    const int b  = blockIdx.z;
    const int i0 = blockIdx.y * 32;
    const int j0 = blockIdx.x * 32;
    const int tx = threadIdx.x;   // 32
    const int ty = threadIdx.y;   // 8
    const size_t base = (size_t)b * NN * NN;

    #pragma unroll
    for (int s = 0; s < 4; s++) {
        const int ii = ty + s * 8;
        const size_t idx = base + (size_t)(i0 + ii) * NN + (j0 + tx);
        const int a = aug[idx];
        const int p = punct[idx];
        tile[ii][tx] = (a == 1) ? (unsigned char)2
                                : ((p == 1) ? (unsigned char)1 : (unsigned char)0);
    }
    __syncthreads();
    #pragma unroll
    for (int s = 0; s < 4; s++) {
        const int jj = ty + s * 8;
        g_maskT[base + (size_t)(j0 + jj) * NN + (i0 + tx)] = tile[tx][jj];
    }
}

// ---------------------------------------------------------------------------
// Kernel 2: compact neighbor lists per (b,j). One warp per target node.
// Disjoint relations share one 512-slot list: r0 grows from index 0,
// r1 grows from index 511 downward.
// ---------------------------------------------------------------------------
__global__ void __launch_bounds__(32)
build_lists_kernel() {
    const int j = blockIdx.x;
    const int b = blockIdx.y;
    const int lane = threadIdx.x;
    const size_t o = (size_t)b * NN + j;
    const unsigned char* __restrict__ row = g_maskT + o * NN;
    unsigned short* __restrict__ lst = g_list + o * NN;

    int c0 = 0, c1 = 0;
    const unsigned lt = (1u << lane) - 1u;

    #pragma unroll 4
    for (int s = 0; s < NN; s += 32) {
        const unsigned char m = row[s + lane];
        const unsigned b0 = __ballot_sync(0xffffffffu, m & 1);
        const unsigned b1 = __ballot_sync(0xffffffffu, m & 2);
        if (m & 1) lst[c0 + __popc(b0 & lt)] = (unsigned short)(s + lane);
        if (m & 2) lst[NN - 1 - (c1 + __popc(b1 & lt))] = (unsigned short)(s + lane);
        c0 += __popc(b0);
        c1 += __popc(b1);
    }
    if (lane == 0) {
        g_cnt[0][o] = c0;
        g_cnt[1][o] = c1;
        g_inv[0][o] = 1.0f / (float)max(c0, 1);
        g_inv[1][o] = 1.0f / (float)max(c1, 1);
    }
}

// ---------------------------------------------------------------------------
// Kernel 3: sparse mean-aggregation via compact lists.
// Block = (j, b), 64 threads; thread t owns channels [4t, 4t+3] (float4).
// ---------------------------------------------------------------------------
__global__ void __launch_bounds__(64)
aggregate_kernel(const float* __restrict__ x, int use_h) {
    const int j = blockIdx.x;
    const int b = blockIdx.y;
    const int t = threadIdx.x;   // 0..63
    const size_t o = (size_t)b * NN + j;

    __shared__ alignas(4) unsigned short slist[NN];
    __shared__ int sn0, sn1;
    __shared__ float si0, si1;
    if (t == 0) {
        sn0 = g_cnt[0][o]; sn1 = g_cnt[1][o];
        si0 = g_inv[0][o]; si1 = g_inv[1][o];
    }
    const unsigned short* __restrict__ lst = g_list + o * NN;
    #pragma unroll
    for (int k = 0; k < NN / 2 / 64; k++)            // 1KB list in 4 passes
        ((unsigned int*)slist)[t + k * 64] = ((const unsigned int*)lst)[t + k * 64];
    __syncthreads();

    const int n0 = sn0, n1 = sn1;
    const float inv0 = si0, inv1 = si1;
    const float4* __restrict__ xb = (const float4*)(
        (use_h ? (const float*)g_h : x) + (size_t)b * NN * DD);

    float4 a0 = make_float4(0.f, 0.f, 0.f, 0.f);
    for (int k = 0; k < n0; k++) {
        const int i = slist[k];
        const float4 v = xb[(size_t)i * (DD / 4) + t];
        a0.x += v.x; a0.y += v.y; a0.z += v.z; a0.w += v.w;
    }
    float4 a1 = make_float4(0.f, 0.f, 0.f, 0.f);
    for (int k = 0; k < n1; k++) {
        const int i = slist[NN - 1 - k];
        const float4 v = xb[(size_t)i * (DD / 4) + t];
        a1.x += v.x; a1.y += v.y; a1.z += v.z; a1.w += v.w;
    }

    a0.x *= inv0; a0.y *= inv0; a0.z *= inv0; a0.w *= inv0;
    a1.x *= inv1; a1.y *= inv1; a1.z *= inv1; a1.w *= inv1;

    float4* __restrict__ out0 = (float4*)(g_agg + o * DD);
    float4* __restrict__ out1 = (float4*)(g_agg + (size_t)BS * NN * DD + o * DD);
    out0[t] = a0;
    out1[t] = a1;
}

// ---------------------------------------------------------------------------
// Kernel 4: fused RGCN transform + bias + ELU as one GEMM:
//   out[m,e] = elu( [X | agg0 | agg1][m,:] @ [Wroot; Wrel0; Wrel1][:,e] + b[e] )
// M=8192, K=768, N=256.  64x64 block tile, 16 K-tile, 4x4 per thread.
// ---------------------------------------------------------------------------
__global__ void __launch_bounds__(256)
rgcn_gemm_kernel(const float* __restrict__ Xin, int in_is_h,
                 const float* __restrict__ Wroot,
                 const float* __restrict__ Wrel,   // [2][256][256]
                 const float* __restrict__ bias,
                 float* __restrict__ Oout, int out_is_h) {
    __shared__ alignas(16) float As[16][64];   // transposed: [k][m]
    __shared__ alignas(16) float Bs[16][64];   // [k][e]

    const float* __restrict__ X = in_is_h ? (const float*)g_h : Xin;
    float* __restrict__ out = out_is_h ? (float*)g_h : Oout;

    const int t  = threadIdx.x;
    const int tx = t & 15;         // e-tile lane
    const int ty = t >> 4;         // m-tile lane
    const int m0 = blockIdx.y * 64;
    const int e0 = blockIdx.x * 64;

    const int arow = t >> 2;       // A loader: row 0..63
    const int akq  = t & 3;        //           k-quad 0..3
    const int bk   = t >> 4;       // B loader: k row 0..15
    const int beq  = t & 15;       //           e-quad 0..15

    const float* A0 = g_agg;
    const float* A1 = g_agg + (size_t)BS * NN * DD;

    float acc[4][4] = {};

    for (int kt = 0; kt < K_TOTAL; kt += 16) {
        const int seg  = kt >> 8;          // 0: root/x, 1: rel0, 2: rel1
        const int ksub = kt & 255;
        const float* __restrict__ Asrc = (seg == 0) ? X : (seg == 1 ? A0 : A1);
        const float* __restrict__ Bsrc =
            (seg == 0) ? Wroot : (Wrel + (size_t)(seg - 1) * DD * DD);

        const float4 av = *(const float4*)&Asrc[(size_t)(m0 + arow) * DD + ksub + akq * 4];
        As[akq * 4 + 0][arow] = av.x;
        As[akq * 4 + 1][arow] = av.y;
        As[akq * 4 + 2][arow] = av.z;
        As[akq * 4 + 3][arow] = av.w;
        *(float4*)&Bs[bk][beq * 4] =
            *(const float4*)&Bsrc[(size_t)(ksub + bk) * DD + e0 + beq * 4];
        __syncthreads();

        #pragma unroll
        for (int kk = 0; kk < 16; kk++) {
            const float4 a4 = *(const float4*)&As[kk][ty * 4];
            const float4 b4 = *(const float4*)&Bs[kk][tx * 4];
            const float a[4]  = {a4.x, a4.y, a4.z, a4.w};
            const float bb[4] = {b4.x, b4.y, b4.z, b4.w};
            #pragma unroll
            for (int p = 0; p < 4; p++)
                #pragma unroll
                for (int q = 0; q < 4; q++)
                    acc[p][q] += a[p] * bb[q];
        }
        __syncthreads();
    }

    #pragma unroll
    for (int p = 0; p < 4; p++) {
        const int m = m0 + ty * 4 + p;
        #pragma unroll
        for (int q = 0; q < 4; q++) {
            const int e = e0 + tx * 4 + q;
            const float v = acc[p][q] + bias[e];
            out[(size_t)m * DD + e] = (v > 0.f) ? v : expm1f(v);
        }
    }
}

// ---------------------------------------------------------------------------
// Launch: masks+lists once, then per layer: list-agg -> fused GEMM+bias+ELU.
// ---------------------------------------------------------------------------
extern "C" void kernel_launch(void* const* d_in, const int* in_sizes, int n_in,
                              void* d_out, int out_size) {
    const float* x       = (const float*)d_in[0];
    const float* w_rel1  = (const float*)d_in[1];
    const float* w_root1 = (const float*)d_in[2];
    const float* b1      = (const float*)d_in[3];
    const float* w_rel2  = (const float*)d_in[4];
    const float* w_root2 = (const float*)d_in[5];
    const float* b2      = (const float*)d_in[6];
    const int* aug   = (const int*)d_in[7];
    const int* punct = (const int*)d_in[8];
    float* out = (float*)d_out;

    build_masks_kernel<<<dim3(NN / 32, NN / 32, BS), dim3(32, 8)>>>(aug, punct);
    build_lists_kernel<<<dim3(NN, BS), 32>>>();

    // Layer 1: agg(x) -> h = elu(gemm)
    aggregate_kernel<<<dim3(NN, BS), 64>>>(x, 0);
    rgcn_gemm_kernel<<<dim3(DD / 64, M_TOTAL / 64), 256>>>(
        x, 0, w_root1, w_rel1, b1, nullptr, 1);

    // Layer 2: agg(h) -> out = elu(gemm)
    aggregate_kernel<<<dim3(NN, BS), 64>>>(nullptr, 1);
    rgcn_gemm_kernel<<<dim3(DD / 64, M_TOTAL / 64), 256>>>(
        nullptr, 1, w_root2, w_rel2, b2, out, 0);
}

// round 5
// speedup vs baseline: 4.6199x; 1.3082x over previous
#include <cuda_runtime.h>
#include <cuda_bf16.h>
#include <cstdint>

#define BS 16
#define NN 512
#define DD 256
#define RR 2
#define M_TOTAL (BS * NN)           // 8192
#define K_TOTAL (3 * DD)            // 768

// Scratch (no allocations allowed).
__device__ __align__(16) unsigned char g_maskT[(size_t)BS * NN * NN];     // [b][j][i]
__device__ __align__(16) unsigned short g_list[(size_t)BS * NN * NN];     // per (b,j): r0 from front, r1 from back
__device__ int   g_cnt[RR][BS * NN];
__device__ float g_inv[RR][BS * NN];
__device__ __align__(16) float g_agg[(size_t)RR * BS * NN * DD];          // [r][b][j][d]
__device__ __align__(16) float g_h[(size_t)BS * NN * DD];                 // layer-1 output

// ---------------------------------------------------------------------------
// Kernel 1: packed transposed masks (adjacency is int32 on device — JAX
// downcasts int64). bit0 = punct (punct==1 && aug!=1), bit1 = aug (aug==1).
// ---------------------------------------------------------------------------
__global__ void build_masks_kernel(const int* __restrict__ aug,
                                   const int* __restrict__ punct) {
    __shared__ unsigned char tile[32][33];
    const int b  = blockIdx.z;
    const int i0 = blockIdx.y * 32;
    const int j0 = blockIdx.x * 32;
    const int tx = threadIdx.x;   // 32
    const int ty = threadIdx.y;   // 8
    const size_t base = (size_t)b * NN * NN;

    #pragma unroll
    for (int s = 0; s < 4; s++) {
        const int ii = ty + s * 8;
        const size_t idx = base + (size_t)(i0 + ii) * NN + (j0 + tx);
        const int a = aug[idx];
        const int p = punct[idx];
        tile[ii][tx] = (a == 1) ? (unsigned char)2
                                : ((p == 1) ? (unsigned char)1 : (unsigned char)0);
    }
    __syncthreads();
    #pragma unroll
    for (int s = 0; s < 4; s++) {
        const int jj = ty + s * 8;
        g_maskT[base + (size_t)(j0 + jj) * NN + (i0 + tx)] = tile[tx][jj];
    }
}

// ---------------------------------------------------------------------------
// Kernel 2: compact neighbor lists per (b,j). One warp per target node.
// ---------------------------------------------------------------------------
__global__ void __launch_bounds__(32)
build_lists_kernel() {
    const int j = blockIdx.x;
    const int b = blockIdx.y;
    const int lane = threadIdx.x;
    const size_t o = (size_t)b * NN + j;
    const unsigned char* __restrict__ row = g_maskT + o * NN;
    unsigned short* __restrict__ lst = g_list + o * NN;

    int c0 = 0, c1 = 0;
    const unsigned lt = (1u << lane) - 1u;

    #pragma unroll 4
    for (int s = 0; s < NN; s += 32) {
        const unsigned char m = row[s + lane];
        const unsigned b0 = __ballot_sync(0xffffffffu, m & 1);
        const unsigned b1 = __ballot_sync(0xffffffffu, m & 2);
        if (m & 1) lst[c0 + __popc(b0 & lt)] = (unsigned short)(s + lane);
        if (m & 2) lst[NN - 1 - (c1 + __popc(b1 & lt))] = (unsigned short)(s + lane);
        c0 += __popc(b0);
        c1 += __popc(b1);
    }
    if (lane == 0) {
        g_cnt[0][o] = c0;
        g_cnt[1][o] = c1;
        g_inv[0][o] = 1.0f / (float)max(c0, 1);
        g_inv[1][o] = 1.0f / (float)max(c1, 1);
    }
}

// ---------------------------------------------------------------------------
// Kernel 3: sparse mean-aggregation via compact lists.
// Block = (j, b), 64 threads; thread t owns channels [4t, 4t+3] (float4).
// ---------------------------------------------------------------------------
__global__ void __launch_bounds__(64)
aggregate_kernel(const float* __restrict__ x, int use_h) {
    const int j = blockIdx.x;
    const int b = blockIdx.y;
    const int t = threadIdx.x;   // 0..63
    const size_t o = (size_t)b * NN + j;

    __shared__ alignas(4) unsigned short slist[NN];
    __shared__ int sn0, sn1;
    __shared__ float si0, si1;
    if (t == 0) {
        sn0 = g_cnt[0][o]; sn1 = g_cnt[1][o];
        si0 = g_inv[0][o]; si1 = g_inv[1][o];
    }
    const unsigned short* __restrict__ lst = g_list + o * NN;
    #pragma unroll
    for (int k = 0; k < NN / 2 / 64; k++)
        ((unsigned int*)slist)[t + k * 64] = ((const unsigned int*)lst)[t + k * 64];
    __syncthreads();

    const int n0 = sn0, n1 = sn1;
    const float inv0 = si0, inv1 = si1;
    const float4* __restrict__ xb = (const float4*)(
        (use_h ? (const float*)g_h : x) + (size_t)b * NN * DD);

    float4 a0 = make_float4(0.f, 0.f, 0.f, 0.f);
    for (int k = 0; k < n0; k++) {
        const int i = slist[k];
        const float4 v = xb[(size_t)i * (DD / 4) + t];
        a0.x += v.x; a0.y += v.y; a0.z += v.z; a0.w += v.w;
    }
    float4 a1 = make_float4(0.f, 0.f, 0.f, 0.f);
    for (int k = 0; k < n1; k++) {
        const int i = slist[NN - 1 - k];
        const float4 v = xb[(size_t)i * (DD / 4) + t];
        a1.x += v.x; a1.y += v.y; a1.z += v.z; a1.w += v.w;
    }

    a0.x *= inv0; a0.y *= inv0; a0.z *= inv0; a0.w *= inv0;
    a1.x *= inv1; a1.y *= inv1; a1.z *= inv1; a1.w *= inv1;

    ((float4*)(g_agg + o * DD))[t] = a0;
    ((float4*)(g_agg + (size_t)BS * NN * DD + o * DD))[t] = a1;
}

// ---------------------------------------------------------------------------
// Kernel 4: fused RGCN transform + bias + ELU as ONE TF32 tensor-core GEMM:
//   out[m,e] = elu( [X | agg0 | agg1][m,:] @ [Wroot; Wrel0; Wrel1][:,e] + b[e] )
// M=8192, K=768, N=256. Block tile 128x128, K-tile 32, 8 warps (4M x 2N),
// warp tile 32x64 via mma.sync.m16n8k8.tf32. Software-pipelined LDG.
// ---------------------------------------------------------------------------
__device__ __forceinline__ uint32_t f2tf32(float f) {
    uint32_t u;
    asm("cvt.rna.tf32.f32 %0, %1;" : "=r"(u) : "f"(f));
    return u;
}

__device__ __forceinline__ void mma_tf32(float c[4], const uint32_t a[4],
                                         uint32_t b0, uint32_t b1) {
    asm volatile(
        "mma.sync.aligned.m16n8k8.row.col.f32.tf32.tf32.f32 "
        "{%0,%1,%2,%3}, {%4,%5,%6,%7}, {%8,%9}, {%0,%1,%2,%3};"
        : "+f"(c[0]), "+f"(c[1]), "+f"(c[2]), "+f"(c[3])
        : "r"(a[0]), "r"(a[1]), "r"(a[2]), "r"(a[3]), "r"(b0), "r"(b1));
}

#define SMS 136   // shared k-row stride (floats): banks (8k+m)%32 distinct

__global__ void __launch_bounds__(256)
rgcn_gemm_kernel(const float* __restrict__ Xin, int in_is_h,
                 const float* __restrict__ Wroot,
                 const float* __restrict__ Wrel,   // [2][256][256]
                 const float* __restrict__ bias,
                 float* __restrict__ Oout, int out_is_h) {
    __shared__ uint32_t As[32][SMS];   // [k][m], tf32 bits
    __shared__ uint32_t Bs[32][SMS];   // [k][n], tf32 bits

    const float* __restrict__ X = in_is_h ? (const float*)g_h : Xin;
    float* __restrict__ out = out_is_h ? (float*)g_h : Oout;

    const int t    = threadIdx.x;
    const int lane = t & 31;
    const int wid  = t >> 5;
    const int wm   = wid & 3;          // warp M index (0..3)
    const int wn   = wid >> 2;         // warp N index (0..1)
    const int gid  = lane >> 2;        // 0..7
    const int tig  = lane & 3;         // 0..3
    const int m0   = blockIdx.y * 128;
    const int e0   = blockIdx.x * 128;

    // A loader: row am (0..127), 16 consecutive k starting at akh
    const int am  = t >> 1;
    const int akh = (t & 1) * 16;
    // B loader: k row bkr (0..31), 4 float4 along n
    const int bkr = t >> 3;
    const int bn0 = (t & 7) * 4;

    const float* A0 = g_agg;
    const float* A1 = g_agg + (size_t)BS * NN * DD;

    float acc[2][8][4] = {};
    float4 ra[4], rb[4];

    // prefetch ktile 0
    {
        const float* __restrict__ Asrc = X;      // seg 0
        const float* __restrict__ Bsrc = Wroot;
        #pragma unroll
        for (int q = 0; q < 4; q++)
            ra[q] = *(const float4*)&Asrc[(size_t)(m0 + am) * DD + akh + q * 4];
        #pragma unroll
        for (int s = 0; s < 4; s++)
            rb[s] = *(const float4*)&Bsrc[(size_t)bkr * DD + e0 + bn0 + s * 32];
    }

    for (int kt = 0; kt < K_TOTAL / 32; kt++) {
        // stage current tile (convert to tf32)
        #pragma unroll
        for (int q = 0; q < 4; q++) {
            As[akh + q * 4 + 0][am] = f2tf32(ra[q].x);
            As[akh + q * 4 + 1][am] = f2tf32(ra[q].y);
            As[akh + q * 4 + 2][am] = f2tf32(ra[q].z);
            As[akh + q * 4 + 3][am] = f2tf32(ra[q].w);
        }
        #pragma unroll
        for (int s = 0; s < 4; s++) {
            uint4 v;
            v.x = f2tf32(rb[s].x); v.y = f2tf32(rb[s].y);
            v.z = f2tf32(rb[s].z); v.w = f2tf32(rb[s].w);
            *(uint4*)&Bs[bkr][bn0 + s * 32] = v;
        }
        __syncthreads();

        // prefetch next tile
        if (kt + 1 < K_TOTAL / 32) {
            const int kg   = (kt + 1) * 32;
            const int seg  = kg >> 8;
            const int ksub = kg & 255;
            const float* __restrict__ Asrc = (seg == 0) ? X : (seg == 1 ? A0 : A1);
            const float* __restrict__ Bsrc =
                (seg == 0) ? Wroot : (Wrel + (size_t)(seg - 1) * DD * DD);
            #pragma unroll
            for (int q = 0; q < 4; q++)
                ra[q] = *(const float4*)&Asrc[(size_t)(m0 + am) * DD + ksub + akh + q * 4];
            #pragma unroll
            for (int s = 0; s < 4; s++)
                rb[s] = *(const float4*)&Bsrc[(size_t)(ksub + bkr) * DD + e0 + bn0 + s * 32];
        }

        // compute 4 k-steps of 8
        #pragma unroll
        for (int ks = 0; ks < 4; ks++) {
            const int kb = ks * 8;
            uint32_t af[2][4];
            #pragma unroll
            for (int mt = 0; mt < 2; mt++) {
                const int m = wm * 32 + mt * 16 + gid;
                af[mt][0] = As[kb + tig][m];
                af[mt][1] = As[kb + tig][m + 8];
                af[mt][2] = As[kb + tig + 4][m];
                af[mt][3] = As[kb + tig + 4][m + 8];
            }
            #pragma unroll
            for (int nt = 0; nt < 8; nt++) {
                const int n = wn * 64 + nt * 8 + gid;
                const uint32_t b0 = Bs[kb + tig][n];
                const uint32_t b1 = Bs[kb + tig + 4][n];
                mma_tf32(acc[0][nt], af[0], b0, b1);
                mma_tf32(acc[1][nt], af[1], b0, b1);
            }
        }
        __syncthreads();
    }

    // epilogue: bias + ELU, float2 stores
    const float2* __restrict__ bias2 = (const float2*)bias;
    #pragma unroll
    for (int mt = 0; mt < 2; mt++) {
        const int mrow = m0 + wm * 32 + mt * 16 + gid;
        #pragma unroll
        for (int nt = 0; nt < 8; nt++) {
            const int col = e0 + wn * 64 + nt * 8 + 2 * tig;
            const float2 bb = bias2[col >> 1];
            float v0 = acc[mt][nt][0] + bb.x;
            float v1 = acc[mt][nt][1] + bb.y;
            float v2 = acc[mt][nt][2] + bb.x;
            float v3 = acc[mt][nt][3] + bb.y;
            v0 = (v0 > 0.f) ? v0 : expm1f(v0);
            v1 = (v1 > 0.f) ? v1 : expm1f(v1);
            v2 = (v2 > 0.f) ? v2 : expm1f(v2);
            v3 = (v3 > 0.f) ? v3 : expm1f(v3);
            *(float2*)&out[(size_t)mrow * DD + col]       = make_float2(v0, v1);
            *(float2*)&out[(size_t)(mrow + 8) * DD + col] = make_float2(v2, v3);
        }
    }
}

// ---------------------------------------------------------------------------
// Launch: masks+lists once, then per layer: list-agg -> TF32 GEMM+bias+ELU.
// ---------------------------------------------------------------------------
extern "C" void kernel_launch(void* const* d_in, const int* in_sizes, int n_in,
                              void* d_out, int out_size) {
    const float* x       = (const float*)d_in[0];
    const float* w_rel1  = (const float*)d_in[1];
    const float* w_root1 = (const float*)d_in[2];
    const float* b1      = (const float*)d_in[3];
    const float* w_rel2  = (const float*)d_in[4];
    const float* w_root2 = (const float*)d_in[5];
    const float* b2      = (const float*)d_in[6];
    const int* aug   = (const int*)d_in[7];
    const int* punct = (const int*)d_in[8];
    float* out = (float*)d_out;

    build_masks_kernel<<<dim3(NN / 32, NN / 32, BS), dim3(32, 8)>>>(aug, punct);
    build_lists_kernel<<<dim3(NN, BS), 32>>>();

    // Layer 1: agg(x) -> h = elu(gemm)
    aggregate_kernel<<<dim3(NN, BS), 64>>>(x, 0);
    rgcn_gemm_kernel<<<dim3(DD / 128, M_TOTAL / 128), 256>>>(
        x, 0, w_root1, w_rel1, b1, nullptr, 1);

    // Layer 2: agg(h) -> out = elu(gemm)
    aggregate_kernel<<<dim3(NN, BS), 64>>>(nullptr, 1);
    rgcn_gemm_kernel<<<dim3(DD / 128, M_TOTAL / 128), 256>>>(
        nullptr, 1, w_root2, w_rel2, b2, out, 0);
}

// round 6
// speedup vs baseline: 6.1656x; 1.3346x over previous
#include <cuda_runtime.h>
#include <cuda_bf16.h>
#include <cstdint>

#define BS 16
#define NN 512
#define DD 256
#define RR 2
#define M_TOTAL (BS * NN)           // 8192
#define K_TOTAL (3 * DD)            // 768
#define BKT 16                      // K-tile
#define NT (K_TOTAL / BKT)          // 48 tiles

// Scratch (no allocations allowed).
__device__ __align__(16) unsigned char g_maskT[(size_t)BS * NN * NN];     // [b][j][i]
__device__ __align__(16) unsigned short g_list[(size_t)BS * NN * NN];     // per (b,j): r0 front, r1 back
__device__ int   g_cnt[RR][BS * NN];
__device__ float g_inv[RR][BS * NN];
__device__ __align__(16) float g_agg[(size_t)RR * BS * NN * DD];          // [r][b][j][d]
__device__ __align__(16) float g_h[(size_t)BS * NN * DD];                 // layer-1 output

// ---------------------------------------------------------------------------
// Kernel 1: packed transposed masks (adjacency is int32 on device — JAX
// downcasts int64). bit0 = punct (punct==1 && aug!=1), bit1 = aug (aug==1).
// ---------------------------------------------------------------------------
__global__ void build_masks_kernel(const int* __restrict__ aug,
                                   const int* __restrict__ punct) {
    __shared__ unsigned char tile[32][33];
    const int b  = blockIdx.z;
    const int i0 = blockIdx.y * 32;
    const int j0 = blockIdx.x * 32;
    const int tx = threadIdx.x;   // 32
    const int ty = threadIdx.y;   // 8
    const size_t base = (size_t)b * NN * NN;

    #pragma unroll
    for (int s = 0; s < 4; s++) {
        const int ii = ty + s * 8;
        const size_t idx = base + (size_t)(i0 + ii) * NN + (j0 + tx);
        const int a = aug[idx];
        const int p = punct[idx];
        tile[ii][tx] = (a == 1) ? (unsigned char)2
                                : ((p == 1) ? (unsigned char)1 : (unsigned char)0);
    }
    __syncthreads();
    #pragma unroll
    for (int s = 0; s < 4; s++) {
        const int jj = ty + s * 8;
        g_maskT[base + (size_t)(j0 + jj) * NN + (i0 + tx)] = tile[tx][jj];
    }
}

// ---------------------------------------------------------------------------
// Kernel 2: compact neighbor lists per (b,j). One warp per target node.
// ---------------------------------------------------------------------------
__global__ void __launch_bounds__(32)
build_lists_kernel() {
    const int j = blockIdx.x;
    const int b = blockIdx.y;
    const int lane = threadIdx.x;
    const size_t o = (size_t)b * NN + j;
    const unsigned char* __restrict__ row = g_maskT + o * NN;
    unsigned short* __restrict__ lst = g_list + o * NN;

    int c0 = 0, c1 = 0;
    const unsigned lt = (1u << lane) - 1u;

    #pragma unroll 4
    for (int s = 0; s < NN; s += 32) {
        const unsigned char m = row[s + lane];
        const unsigned b0 = __ballot_sync(0xffffffffu, m & 1);
        const unsigned b1 = __ballot_sync(0xffffffffu, m & 2);
        if (m & 1) lst[c0 + __popc(b0 & lt)] = (unsigned short)(s + lane);
        if (m & 2) lst[NN - 1 - (c1 + __popc(b1 & lt))] = (unsigned short)(s + lane);
        c0 += __popc(b0);
        c1 += __popc(b1);
    }
    if (lane == 0) {
        g_cnt[0][o] = c0;
        g_cnt[1][o] = c1;
        g_inv[0][o] = 1.0f / (float)max(c0, 1);
        g_inv[1][o] = 1.0f / (float)max(c1, 1);
    }
}

// ---------------------------------------------------------------------------
// Kernel 3: sparse mean-aggregation via compact lists.
// Block = (j, b), 64 threads; thread t owns channels [4t, 4t+3] (float4).
// ---------------------------------------------------------------------------
__global__ void __launch_bounds__(64)
aggregate_kernel(const float* __restrict__ x, int use_h) {
    const int j = blockIdx.x;
    const int b = blockIdx.y;
    const int t = threadIdx.x;   // 0..63
    const size_t o = (size_t)b * NN + j;

    __shared__ alignas(4) unsigned short slist[NN];
    __shared__ int sn0, sn1;
    __shared__ float si0, si1;
    if (t == 0) {
        sn0 = g_cnt[0][o]; sn1 = g_cnt[1][o];
        si0 = g_inv[0][o]; si1 = g_inv[1][o];
    }
    const unsigned short* __restrict__ lst = g_list + o * NN;
    #pragma unroll
    for (int k = 0; k < NN / 2 / 64; k++)
        ((unsigned int*)slist)[t + k * 64] = ((const unsigned int*)lst)[t + k * 64];
    __syncthreads();

    const int n0 = sn0, n1 = sn1;
    const float inv0 = si0, inv1 = si1;
    const float4* __restrict__ xb = (const float4*)(
        (use_h ? (const float*)g_h : x) + (size_t)b * NN * DD);

    float4 a0 = make_float4(0.f, 0.f, 0.f, 0.f);
    for (int k = 0; k < n0; k++) {
        const int i = slist[k];
        const float4 v = xb[(size_t)i * (DD / 4) + t];
        a0.x += v.x; a0.y += v.y; a0.z += v.z; a0.w += v.w;
    }
    float4 a1 = make_float4(0.f, 0.f, 0.f, 0.f);
    for (int k = 0; k < n1; k++) {
        const int i = slist[NN - 1 - k];
        const float4 v = xb[(size_t)i * (DD / 4) + t];
        a1.x += v.x; a1.y += v.y; a1.z += v.z; a1.w += v.w;
    }

    a0.x *= inv0; a0.y *= inv0; a0.z *= inv0; a0.w *= inv0;
    a1.x *= inv1; a1.y *= inv1; a1.z *= inv1; a1.w *= inv1;

    ((float4*)(g_agg + o * DD))[t] = a0;
    ((float4*)(g_agg + (size_t)BS * NN * DD + o * DD))[t] = a1;
}

// ---------------------------------------------------------------------------
// Kernel 4: fused RGCN transform + bias + ELU as ONE TF32 tensor-core GEMM,
// double-buffered smem (BK=16), one __syncthreads per K-tile.
//   out[m,e] = elu( [X | agg0 | agg1][m,:] @ [Wroot; Wrel0; Wrel1][:,e] + b[e] )
// M=8192, K=768, N=256. Block tile 128x128, 8 warps (4M x 2N), warp 32x64.
// ---------------------------------------------------------------------------
__device__ __forceinline__ uint32_t f2tf32(float f) {
    uint32_t u;
    asm("cvt.rna.tf32.f32 %0, %1;" : "=r"(u) : "f"(f));
    return u;
}

__device__ __forceinline__ void mma_tf32(float c[4], const uint32_t a[4],
                                         uint32_t b0, uint32_t b1) {
    asm volatile(
        "mma.sync.aligned.m16n8k8.row.col.f32.tf32.tf32.f32 "
        "{%0,%1,%2,%3}, {%4,%5,%6,%7}, {%8,%9}, {%0,%1,%2,%3};"
        : "+f"(c[0]), "+f"(c[1]), "+f"(c[2]), "+f"(c[3])
        : "r"(a[0]), "r"(a[1]), "r"(a[2]), "r"(a[3]), "r"(b0), "r"(b1));
}

#define SMS 136   // shared k-row stride (floats): fragment LDS conflict-free

__global__ void __launch_bounds__(256)
rgcn_gemm_kernel(const float* __restrict__ Xin, int in_is_h,
                 const float* __restrict__ Wroot,
                 const float* __restrict__ Wrel,   // [2][256][256]
                 const float* __restrict__ bias,
                 float* __restrict__ Oout, int out_is_h) {
    __shared__ uint32_t As[2][BKT][SMS];   // [stage][k][m], tf32 bits
    __shared__ uint32_t Bs[2][BKT][SMS];   // [stage][k][n], tf32 bits

    const float* __restrict__ X = in_is_h ? (const float*)g_h : Xin;
    float* __restrict__ out = out_is_h ? (float*)g_h : Oout;

    const int t    = threadIdx.x;
    const int lane = t & 31;
    const int wid  = t >> 5;
    const int wm   = wid & 3;          // warp M index (0..3)
    const int wn   = wid >> 2;         // warp N index (0..1)
    const int gid  = lane >> 2;        // 0..7
    const int tig  = lane & 3;         // 0..3
    const int m0   = blockIdx.y * 128;
    const int e0   = blockIdx.x * 128;

    // A loader: row am (0..127), 8 consecutive k starting at akh
    const int am  = t >> 1;
    const int akh = (t & 1) * 8;
    // B loader: k row bkr (0..15), 8 consecutive n at bn0
    const int bkr = t >> 4;
    const int bn0 = (t & 15) * 8;

    const float* A0 = g_agg;
    const float* A1 = g_agg + (size_t)BS * NN * DD;

    float acc[2][8][4] = {};
    float4 ra[2], rb[2];

    // prefetch + stage ktile 0 (seg 0: X, Wroot)
    #pragma unroll
    for (int q = 0; q < 2; q++)
        ra[q] = *(const float4*)&X[(size_t)(m0 + am) * DD + akh + q * 4];
    #pragma unroll
    for (int s = 0; s < 2; s++)
        rb[s] = *(const float4*)&Wroot[(size_t)bkr * DD + e0 + bn0 + s * 4];
    #pragma unroll
    for (int q = 0; q < 2; q++) {
        As[0][akh + q * 4 + 0][am] = f2tf32(ra[q].x);
        As[0][akh + q * 4 + 1][am] = f2tf32(ra[q].y);
        As[0][akh + q * 4 + 2][am] = f2tf32(ra[q].z);
        As[0][akh + q * 4 + 3][am] = f2tf32(ra[q].w);
    }
    #pragma unroll
    for (int s = 0; s < 2; s++) {
        uint4 v;
        v.x = f2tf32(rb[s].x); v.y = f2tf32(rb[s].y);
        v.z = f2tf32(rb[s].z); v.w = f2tf32(rb[s].w);
        *(uint4*)&Bs[0][bkr][bn0 + s * 4] = v;
    }
    __syncthreads();

    int st = 0;
    for (int kt = 0; kt < NT; kt++) {
        const bool more = (kt + 1 < NT);
        if (more) {
            const int kg   = (kt + 1) * BKT;
            const int seg  = kg >> 8;
            const int ksub = kg & 255;
            const float* __restrict__ Asrc = (seg == 0) ? X : (seg == 1 ? A0 : A1);
            const float* __restrict__ Bsrc =
                (seg == 0) ? Wroot : (Wrel + (size_t)(seg - 1) * DD * DD);
            #pragma unroll
            for (int q = 0; q < 2; q++)
                ra[q] = *(const float4*)&Asrc[(size_t)(m0 + am) * DD + ksub + akh + q * 4];
            #pragma unroll
            for (int s = 0; s < 2; s++)
                rb[s] = *(const float4*)&Bsrc[(size_t)(ksub + bkr) * DD + e0 + bn0 + s * 4];
        }

        // compute on stage st: 2 k-steps of 8
        #pragma unroll
        for (int ks = 0; ks < 2; ks++) {
            const int kb = ks * 8;
            uint32_t af[2][4];
            #pragma unroll
            for (int mt = 0; mt < 2; mt++) {
                const int m = wm * 32 + mt * 16 + gid;
                af[mt][0] = As[st][kb + tig][m];
                af[mt][1] = As[st][kb + tig][m + 8];
                af[mt][2] = As[st][kb + tig + 4][m];
                af[mt][3] = As[st][kb + tig + 4][m + 8];
            }
            #pragma unroll
            for (int nt = 0; nt < 8; nt++) {
                const int n = wn * 64 + nt * 8 + gid;
                const uint32_t b0 = Bs[st][kb + tig][n];
                const uint32_t b1 = Bs[st][kb + tig + 4][n];
                mma_tf32(acc[0][nt], af[0], b0, b1);
                mma_tf32(acc[1][nt], af[1], b0, b1);
            }
        }

        // stage next tile into the other buffer (overlaps with MMA above)
        if (more) {
            const int ns = st ^ 1;
            #pragma unroll
            for (int q = 0; q < 2; q++) {
                As[ns][akh + q * 4 + 0][am] = f2tf32(ra[q].x);
                As[ns][akh + q * 4 + 1][am] = f2tf32(ra[q].y);
                As[ns][akh + q * 4 + 2][am] = f2tf32(ra[q].z);
                As[ns][akh + q * 4 + 3][am] = f2tf32(ra[q].w);
            }
            #pragma unroll
            for (int s = 0; s < 2; s++) {
                uint4 v;
                v.x = f2tf32(rb[s].x); v.y = f2tf32(rb[s].y);
                v.z = f2tf32(rb[s].z); v.w = f2tf32(rb[s].w);
                *(uint4*)&Bs[ns][bkr][bn0 + s * 4] = v;
            }
        }
        __syncthreads();
        st ^= 1;
    }

    // epilogue: bias + ELU, float2 stores
    const float2* __restrict__ bias2 = (const float2*)bias;
    #pragma unroll
    for (int mt = 0; mt < 2; mt++) {
        const int mrow = m0 + wm * 32 + mt * 16 + gid;
        #pragma unroll
        for (int nt = 0; nt < 8; nt++) {
            const int col = e0 + wn * 64 + nt * 8 + 2 * tig;
            const float2 bb = bias2[col >> 1];
            float v0 = acc[mt][nt][0] + bb.x;
            float v1 = acc[mt][nt][1] + bb.y;
            float v2 = acc[mt][nt][2] + bb.x;
            float v3 = acc[mt][nt][3] + bb.y;
            v0 = (v0 > 0.f) ? v0 : expm1f(v0);
            v1 = (v1 > 0.f) ? v1 : expm1f(v1);
            v2 = (v2 > 0.f) ? v2 : expm1f(v2);
            v3 = (v3 > 0.f) ? v3 : expm1f(v3);
            *(float2*)&out[(size_t)mrow * DD + col]       = make_float2(v0, v1);
            *(float2*)&out[(size_t)(mrow + 8) * DD + col] = make_float2(v2, v3);
        }
    }
}

// ---------------------------------------------------------------------------
// Launch: masks+lists once, then per layer: list-agg -> TF32 GEMM+bias+ELU.
// ---------------------------------------------------------------------------
extern "C" void kernel_launch(void* const* d_in, const int* in_sizes, int n_in,
                              void* d_out, int out_size) {
    const float* x       = (const float*)d_in[0];
    const float* w_rel1  = (const float*)d_in[1];
    const float* w_root1 = (const float*)d_in[2];
    const float* b1      = (const float*)d_in[3];
    const float* w_rel2  = (const float*)d_in[4];
    const float* w_root2 = (const float*)d_in[5];
    const float* b2      = (const float*)d_in[6];
    const int* aug   = (const int*)d_in[7];
    const int* punct = (const int*)d_in[8];
    float* out = (float*)d_out;

    build_masks_kernel<<<dim3(NN / 32, NN / 32, BS), dim3(32, 8)>>>(aug, punct);
    build_lists_kernel<<<dim3(NN, BS), 32>>>();

    // Layer 1: agg(x) -> h = elu(gemm)
    aggregate_kernel<<<dim3(NN, BS), 64>>>(x, 0);
    rgcn_gemm_kernel<<<dim3(DD / 128, M_TOTAL / 128), 256>>>(
        x, 0, w_root1, w_rel1, b1, nullptr, 1);

    // Layer 2: agg(h) -> out = elu(gemm)
    aggregate_kernel<<<dim3(NN, BS), 64>>>(nullptr, 1);
    rgcn_gemm_kernel<<<dim3(DD / 128, M_TOTAL / 128), 256>>>(
        nullptr, 1, w_root2, w_rel2, b2, out, 0);
}

// round 7
// speedup vs baseline: 7.0053x; 1.1362x over previous
#include <cuda_runtime.h>
#include <cuda_bf16.h>
#include <cstdint>

#define BS 16
#define NN 512
#define DD 256
#define RR 2
#define M_TOTAL (BS * NN)           // 8192
#define K_TOTAL (3 * DD)            // 768
#define BKT 16                      // K-tile
#define NT (K_TOTAL / BKT)          // 48 tiles
#define STG 3                       // cp.async stages
#define ACAT_L ((size_t)M_TOTAL * K_TOTAL)   // per-layer A size
#define W_L    ((size_t)K_TOTAL * DD)        // per-layer W size

// Scratch (no allocations allowed).
__device__ __align__(16) unsigned char g_maskT[(size_t)BS * NN * NN];   // [b][j][i]
__device__ __align__(16) unsigned short g_list[(size_t)BS * NN * NN];   // per (b,j): r0 front, r1 back
__device__ int   g_cnt[RR][BS * NN];
__device__ float g_inv[RR][BS * NN];
__device__ __align__(16) uint32_t g_acat[2 * ACAT_L];   // tf32 [layer][m][768] = [x|agg0|agg1]
__device__ __align__(16) uint32_t g_w[2 * W_L];         // tf32 [layer][768][256] = [Wroot;Wrel0;Wrel1]
__device__ __align__(16) float g_h[(size_t)BS * NN * DD];   // layer-1 output (fp32, for aggregation)

__device__ __forceinline__ uint32_t f2tf32(float f) {
    uint32_t u;
    asm("cvt.rna.tf32.f32 %0, %1;" : "=r"(u) : "f"(f));
    return u;
}

// ---------------------------------------------------------------------------
// Kernel 1: packed transposed masks (adjacency is int32 on device — JAX
// downcasts int64). bit0 = punct (punct==1 && aug!=1), bit1 = aug (aug==1).
// ---------------------------------------------------------------------------
__global__ void build_masks_kernel(const int* __restrict__ aug,
                                   const int* __restrict__ punct) {
    __shared__ unsigned char tile[32][33];
    const int b  = blockIdx.z;
    const int i0 = blockIdx.y * 32;
    const int j0 = blockIdx.x * 32;
    const int tx = threadIdx.x;   // 32
    const int ty = threadIdx.y;   // 8
    const size_t base = (size_t)b * NN * NN;

    #pragma unroll
    for (int s = 0; s < 4; s++) {
        const int ii = ty + s * 8;
        const size_t idx = base + (size_t)(i0 + ii) * NN + (j0 + tx);
        const int a = aug[idx];
        const int p = punct[idx];
        tile[ii][tx] = (a == 1) ? (unsigned char)2
                                : ((p == 1) ? (unsigned char)1 : (unsigned char)0);
    }
    __syncthreads();
    #pragma unroll
    for (int s = 0; s < 4; s++) {
        const int jj = ty + s * 8;
        g_maskT[base + (size_t)(j0 + jj) * NN + (i0 + tx)] = tile[tx][jj];
    }
}

// ---------------------------------------------------------------------------
// Kernel 2: compact neighbor lists per (b,j). One warp per target node.
// ---------------------------------------------------------------------------
__global__ void __launch_bounds__(32)
build_lists_kernel() {
    const int j = blockIdx.x;
    const int b = blockIdx.y;
    const int lane = threadIdx.x;
    const size_t o = (size_t)b * NN + j;
    const unsigned char* __restrict__ row = g_maskT + o * NN;
    unsigned short* __restrict__ lst = g_list + o * NN;

    int c0 = 0, c1 = 0;
    const unsigned lt = (1u << lane) - 1u;

    #pragma unroll 4
    for (int s = 0; s < NN; s += 32) {
        const unsigned char m = row[s + lane];
        const unsigned b0 = __ballot_sync(0xffffffffu, m & 1);
        const unsigned b1 = __ballot_sync(0xffffffffu, m & 2);
        if (m & 1) lst[c0 + __popc(b0 & lt)] = (unsigned short)(s + lane);
        if (m & 2) lst[NN - 1 - (c1 + __popc(b1 & lt))] = (unsigned short)(s + lane);
        c0 += __popc(b0);
        c1 += __popc(b1);
    }
    if (lane == 0) {
        g_cnt[0][o] = c0;
        g_cnt[1][o] = c1;
        g_inv[0][o] = 1.0f / (float)max(c0, 1);
        g_inv[1][o] = 1.0f / (float)max(c1, 1);
    }
}

// ---------------------------------------------------------------------------
// Kernel 3: convert x and both layers' weights to tf32, into the concat
// layouts g_acat[0] (seg0) and g_w[0..1]. Grid-stride over float4 items.
// ---------------------------------------------------------------------------
#define XF4 (M_TOTAL * DD / 4)           // 524288
#define WF4L (K_TOTAL * DD / 4)          // 49152 per layer
#define ROOTF4 (DD * DD / 4)             // 16384

__global__ void cvt_inputs_kernel(const float* __restrict__ x,
                                  const float* __restrict__ wroot1,
                                  const float* __restrict__ wrel1,
                                  const float* __restrict__ wroot2,
                                  const float* __restrict__ wrel2) {
    const int total = XF4 + 2 * WF4L;
    for (int idx = blockIdx.x * blockDim.x + threadIdx.x; idx < total;
         idx += gridDim.x * blockDim.x) {
        float4 v;
        uint32_t* dst;
        if (idx < XF4) {
            const int m = idx >> 6;            // DD/4 = 64
            const int dq = idx & 63;
            v = ((const float4*)x)[idx];
            dst = g_acat + (size_t)m * K_TOTAL + dq * 4;
        } else {
            const int j = idx - XF4;
            const int L = j / WF4L;
            const int j2 = j - L * WF4L;
            const float4* src = (j2 < ROOTF4)
                ? ((const float4*)(L ? wroot2 : wroot1)) + j2
                : ((const float4*)(L ? wrel2 : wrel1)) + (j2 - ROOTF4);
            v = *src;
            dst = g_w + (size_t)L * W_L + (size_t)j2 * 4;
        }
        uint4 u;
        u.x = f2tf32(v.x); u.y = f2tf32(v.y);
        u.z = f2tf32(v.z); u.w = f2tf32(v.w);
        *(uint4*)dst = u;
    }
}

// ---------------------------------------------------------------------------
// Kernel 4: sparse mean-aggregation via compact lists; writes tf32 directly
// into g_acat[layer] segments 1 and 2. Block = (j, b), 64 threads.
// ---------------------------------------------------------------------------
__global__ void __launch_bounds__(64)
aggregate_kernel(const float* __restrict__ x, int layer) {
    const int j = blockIdx.x;
    const int b = blockIdx.y;
    const int t = threadIdx.x;   // 0..63
    const size_t o = (size_t)b * NN + j;

    __shared__ alignas(4) unsigned short slist[NN];
    __shared__ int sn0, sn1;
    __shared__ float si0, si1;
    if (t == 0) {
        sn0 = g_cnt[0][o]; sn1 = g_cnt[1][o];
        si0 = g_inv[0][o]; si1 = g_inv[1][o];
    }
    const unsigned short* __restrict__ lst = g_list + o * NN;
    #pragma unroll
    for (int k = 0; k < NN / 2 / 64; k++)
        ((unsigned int*)slist)[t + k * 64] = ((const unsigned int*)lst)[t + k * 64];
    __syncthreads();

    const int n0 = sn0, n1 = sn1;
    const float inv0 = si0, inv1 = si1;
    const float4* __restrict__ xb = (const float4*)(
        (layer ? (const float*)g_h : x) + (size_t)b * NN * DD);

    float4 a0 = make_float4(0.f, 0.f, 0.f, 0.f);
    for (int k = 0; k < n0; k++) {
        const int i = slist[k];
        const float4 v = xb[(size_t)i * (DD / 4) + t];
        a0.x += v.x; a0.y += v.y; a0.z += v.z; a0.w += v.w;
    }
    float4 a1 = make_float4(0.f, 0.f, 0.f, 0.f);
    for (int k = 0; k < n1; k++) {
        const int i = slist[NN - 1 - k];
        const float4 v = xb[(size_t)i * (DD / 4) + t];
        a1.x += v.x; a1.y += v.y; a1.z += v.z; a1.w += v.w;
    }

    uint32_t* __restrict__ base =
        g_acat + (size_t)layer * ACAT_L + o * K_TOTAL;
    uint4 u0, u1;
    u0.x = f2tf32(a0.x * inv0); u0.y = f2tf32(a0.y * inv0);
    u0.z = f2tf32(a0.z * inv0); u0.w = f2tf32(a0.w * inv0);
    u1.x = f2tf32(a1.x * inv1); u1.y = f2tf32(a1.y * inv1);
    u1.z = f2tf32(a1.z * inv1); u1.w = f2tf32(a1.w * inv1);
    ((uint4*)(base + DD))[t]     = u0;   // seg1
    ((uint4*)(base + 2 * DD))[t] = u1;   // seg2
}

// ---------------------------------------------------------------------------
// Kernel 5: TF32 tensor-core GEMM + bias + ELU, cp.async 3-stage pipeline.
//   out[m,e] = elu( Acat[m,:] @ W[:,e] + bias[e] )
// M=8192, K=768, N=256. Block tile 64x128, 4 warps (2M x 2N), warp 32x64.
// layer==0: writes g_h (fp32) and g_acat[1] seg0 (tf32).
// layer==1: writes dout (fp32).
// ---------------------------------------------------------------------------
__device__ __forceinline__ void mma_tf32(float c[4], const uint32_t a[4],
                                         uint32_t b0, uint32_t b1) {
    asm volatile(
        "mma.sync.aligned.m16n8k8.row.col.f32.tf32.tf32.f32 "
        "{%0,%1,%2,%3}, {%4,%5,%6,%7}, {%8,%9}, {%0,%1,%2,%3};"
        : "+f"(c[0]), "+f"(c[1]), "+f"(c[2]), "+f"(c[3])
        : "r"(a[0]), "r"(a[1]), "r"(a[2]), "r"(a[3]), "r"(b0), "r"(b1));
}

__device__ __forceinline__ void cp16(uint32_t dst, const void* src) {
    asm volatile("cp.async.cg.shared.global [%0], [%1], 16;"
                 :: "r"(dst), "l"(src));
}

#define ASTR 20    // A shared stride (floats): [m][k], conflict-free fragments
#define BSTR 132   // B shared stride (floats): [k][n], conflict-free fragments

__global__ void __launch_bounds__(128)
rgcn_gemm_kernel(int layer, const float* __restrict__ bias,
                 float* __restrict__ dout) {
    __shared__ uint32_t As[STG][64][ASTR];    // [stage][m][k]
    __shared__ uint32_t Bs[STG][BKT][BSTR];   // [stage][k][n]

    const uint32_t* __restrict__ Ag = g_acat + (size_t)layer * ACAT_L;
    const uint32_t* __restrict__ Bg = g_w + (size_t)layer * W_L;

    const int t    = threadIdx.x;
    const int lane = t & 31;
    const int wid  = t >> 5;
    const int wm   = wid & 1;          // warp M index (0..1)
    const int wn   = wid >> 1;         // warp N index (0..1)
    const int gid  = lane >> 2;        // 0..7
    const int tig  = lane & 3;         // 0..3
    const int m0   = blockIdx.y * 64;
    const int e0   = blockIdx.x * 128;

    const uint32_t asb = (uint32_t)__cvta_generic_to_shared(As);
    const uint32_t bsb = (uint32_t)__cvta_generic_to_shared(Bs);

    // copy mappings
    const int ar0 = t >> 2;            // A chunk 0: row 0..31
    const int ako = (t & 3) << 2;      // k offset 0/4/8/12
    const int br0 = t >> 5;            // B chunk i: row = br0 + 4*i
    const int bno = (t & 31) << 2;     // n offset

    auto issue_tile = [&](int tile) {
        if (tile < NT) {
            const int stage = tile % STG;
            const int kg = tile * BKT;
            #pragma unroll
            for (int i = 0; i < 2; i++) {
                const int r = ar0 + 32 * i;
                cp16(asb + (uint32_t)(((stage * 64 + r) * ASTR + ako) * 4),
                     Ag + (size_t)(m0 + r) * K_TOTAL + kg + ako);
            }
            #pragma unroll
            for (int i = 0; i < 4; i++) {
                const int r = br0 + 4 * i;
                cp16(bsb + (uint32_t)(((stage * BKT + r) * BSTR + bno) * 4),
                     Bg + (size_t)(kg + r) * DD + e0 + bno);
            }
        }
        asm volatile("cp.async.commit_group;");
    };

    // prologue: tiles 0 .. STG-2
    issue_tile(0);
    issue_tile(1);

    float acc[2][8][4] = {};

    for (int kt = 0; kt < NT; kt++) {
        asm volatile("cp.async.wait_group %0;" :: "n"(STG - 2));
        __syncthreads();

        issue_tile(kt + STG - 1);

        const int st = kt % STG;
        #pragma unroll
        for (int ks = 0; ks < 2; ks++) {
            const int kb = ks * 8;
            uint32_t af[2][4];
            #pragma unroll
            for (int mt = 0; mt < 2; mt++) {
                const int m = wm * 32 + mt * 16 + gid;
                af[mt][0] = As[st][m][kb + tig];
                af[mt][1] = As[st][m + 8][kb + tig];
                af[mt][2] = As[st][m][kb + tig + 4];
                af[mt][3] = As[st][m + 8][kb + tig + 4];
            }
            #pragma unroll
            for (int nt = 0; nt < 8; nt++) {
                const int n = wn * 64 + nt * 8 + gid;
                const uint32_t b0 = Bs[st][kb + tig][n];
                const uint32_t b1 = Bs[st][kb + tig + 4][n];
                mma_tf32(acc[0][nt], af[0], b0, b1);
                mma_tf32(acc[1][nt], af[1], b0, b1);
            }
        }
    }

    // epilogue: bias + ELU
    float* __restrict__ outf = (layer == 0) ? (float*)g_h : dout;
    uint32_t* __restrict__ outt = g_acat + ACAT_L;   // layer-1 seg0 (only used if layer==0)
    const float2* __restrict__ bias2 = (const float2*)bias;

    #pragma unroll
    for (int mt = 0; mt < 2; mt++) {
        const int mrow = m0 + wm * 32 + mt * 16 + gid;
        #pragma unroll
        for (int nt = 0; nt < 8; nt++) {
            const int col = e0 + wn * 64 + nt * 8 + 2 * tig;
            const float2 bb = bias2[col >> 1];
            float v0 = acc[mt][nt][0] + bb.x;
            float v1 = acc[mt][nt][1] + bb.y;
            float v2 = acc[mt][nt][2] + bb.x;
            float v3 = acc[mt][nt][3] + bb.y;
            v0 = (v0 > 0.f) ? v0 : expm1f(v0);
            v1 = (v1 > 0.f) ? v1 : expm1f(v1);
            v2 = (v2 > 0.f) ? v2 : expm1f(v2);
            v3 = (v3 > 0.f) ? v3 : expm1f(v3);
            *(float2*)&outf[(size_t)mrow * DD + col]       = make_float2(v0, v1);
            *(float2*)&outf[(size_t)(mrow + 8) * DD + col] = make_float2(v2, v3);
            if (layer == 0) {
                uint2 u0; u0.x = f2tf32(v0); u0.y = f2tf32(v1);
                uint2 u1; u1.x = f2tf32(v2); u1.y = f2tf32(v3);
                *(uint2*)&outt[(size_t)mrow * K_TOTAL + col]       = u0;
                *(uint2*)&outt[(size_t)(mrow + 8) * K_TOTAL + col] = u1;
            }
        }
    }
}

// ---------------------------------------------------------------------------
// Launch: masks+lists+cvt once, then per layer: agg -> TF32 GEMM+bias+ELU.
// ---------------------------------------------------------------------------
extern "C" void kernel_launch(void* const* d_in, const int* in_sizes, int n_in,
                              void* d_out, int out_size) {
    const float* x       = (const float*)d_in[0];
    const float* w_rel1  = (const float*)d_in[1];
    const float* w_root1 = (const float*)d_in[2];
    const float* b1      = (const float*)d_in[3];
    const float* w_rel2  = (const float*)d_in[4];
    const float* w_root2 = (const float*)d_in[5];
    const float* b2      = (const float*)d_in[6];
    const int* aug   = (const int*)d_in[7];
    const int* punct = (const int*)d_in[8];
    float* out = (float*)d_out;

    build_masks_kernel<<<dim3(NN / 32, NN / 32, BS), dim3(32, 8)>>>(aug, punct);
    build_lists_kernel<<<dim3(NN, BS), 32>>>();
    cvt_inputs_kernel<<<1184, 256>>>(x, w_root1, w_rel1, w_root2, w_rel2);

    // Layer 1: agg(x) -> acat0 seg1/2; gemm -> g_h + acat1 seg0
    aggregate_kernel<<<dim3(NN, BS), 64>>>(x, 0);
    rgcn_gemm_kernel<<<dim3(DD / 128, M_TOTAL / 64), 128>>>(0, b1, nullptr);

    // Layer 2: agg(h) -> acat1 seg1/2; gemm -> out
    aggregate_kernel<<<dim3(NN, BS), 64>>>(nullptr, 1);
    rgcn_gemm_kernel<<<dim3(DD / 128, M_TOTAL / 64), 128>>>(1, b2, out);
}

// round 8
// speedup vs baseline: 7.1946x; 1.0270x over previous
#include <cuda_runtime.h>
#include <cuda_bf16.h>
#include <cstdint>

#define BS 16
#define NN 512
#define DD 256
#define RR 2
#define M_TOTAL (BS * NN)           // 8192
#define K_TOTAL (3 * DD)            // 768
#define BKT 16                      // K-tile
#define NT (K_TOTAL / BKT)          // 48 tiles
#define STG 3                       // cp.async stages
#define ACAT_L ((size_t)M_TOTAL * K_TOTAL)   // per-layer A size
#define W_L    ((size_t)K_TOTAL * DD)        // per-layer W size

// Scratch (no allocations allowed).
__device__ __align__(16) unsigned char g_maskT[(size_t)BS * NN * NN];   // [b][j][i]
__device__ __align__(16) unsigned short g_list[(size_t)BS * NN * NN];   // per (b,j): r0 front, r1 back
__device__ int   g_cnt[RR][BS * NN];
__device__ float g_inv[RR][BS * NN];
__device__ __align__(16) uint32_t g_acat[2 * ACAT_L];   // tf32 [layer][m][768] = [x|agg0|agg1]
__device__ __align__(16) uint32_t g_w[2 * W_L];         // tf32 [layer][768][256] = [Wroot;Wrel0;Wrel1]
__device__ __align__(16) float g_h[(size_t)BS * NN * DD];   // layer-1 output (fp32, for aggregation)

__device__ __forceinline__ uint32_t f2tf32(float f) {
    uint32_t u;
    asm("cvt.rna.tf32.f32 %0, %1;" : "=r"(u) : "f"(f));
    return u;
}

// ---------------------------------------------------------------------------
// Kernel 1: packed transposed masks (adjacency is int32 on device — JAX
// downcasts int64). bit0 = punct (punct==1 && aug!=1), bit1 = aug (aug==1).
// ---------------------------------------------------------------------------
__global__ void build_masks_kernel(const int* __restrict__ aug,
                                   const int* __restrict__ punct) {
    __shared__ unsigned char tile[32][33];
    const int b  = blockIdx.z;
    const int i0 = blockIdx.y * 32;
    const int j0 = blockIdx.x * 32;
    const int tx = threadIdx.x;   // 32
    const int ty = threadIdx.y;   // 8
    const size_t base = (size_t)b * NN * NN;

    #pragma unroll
    for (int s = 0; s < 4; s++) {
        const int ii = ty + s * 8;
        const size_t idx = base + (size_t)(i0 + ii) * NN + (j0 + tx);
        const int a = aug[idx];
        const int p = punct[idx];
        tile[ii][tx] = (a == 1) ? (unsigned char)2
                                : ((p == 1) ? (unsigned char)1 : (unsigned char)0);
    }
    __syncthreads();
    #pragma unroll
    for (int s = 0; s < 4; s++) {
        const int jj = ty + s * 8;
        g_maskT[base + (size_t)(j0 + jj) * NN + (i0 + tx)] = tile[tx][jj];
    }
}

// ---------------------------------------------------------------------------
// Kernel 2: compact neighbor lists per (b,j). One warp per target node.
// ---------------------------------------------------------------------------
__global__ void __launch_bounds__(32)
build_lists_kernel() {
    const int j = blockIdx.x;
    const int b = blockIdx.y;
    const int lane = threadIdx.x;
    const size_t o = (size_t)b * NN + j;
    const unsigned char* __restrict__ row = g_maskT + o * NN;
    unsigned short* __restrict__ lst = g_list + o * NN;

    int c0 = 0, c1 = 0;
    const unsigned lt = (1u << lane) - 1u;

    #pragma unroll 4
    for (int s = 0; s < NN; s += 32) {
        const unsigned char m = row[s + lane];
        const unsigned b0 = __ballot_sync(0xffffffffu, m & 1);
        const unsigned b1 = __ballot_sync(0xffffffffu, m & 2);
        if (m & 1) lst[c0 + __popc(b0 & lt)] = (unsigned short)(s + lane);
        if (m & 2) lst[NN - 1 - (c1 + __popc(b1 & lt))] = (unsigned short)(s + lane);
        c0 += __popc(b0);
        c1 += __popc(b1);
    }
    if (lane == 0) {
        g_cnt[0][o] = c0;
        g_cnt[1][o] = c1;
        g_inv[0][o] = 1.0f / (float)max(c0, 1);
        g_inv[1][o] = 1.0f / (float)max(c1, 1);
    }
}

// ---------------------------------------------------------------------------
// Kernel 3: convert x and both layers' weights to tf32, into the concat
// layouts g_acat[0] (seg0) and g_w[0..1]. Grid-stride over float4 items.
// ---------------------------------------------------------------------------
#define XF4 (M_TOTAL * DD / 4)           // 524288
#define WF4L (K_TOTAL * DD / 4)          // 49152 per layer
#define ROOTF4 (DD * DD / 4)             // 16384

__global__ void cvt_inputs_kernel(const float* __restrict__ x,
                                  const float* __restrict__ wroot1,
                                  const float* __restrict__ wrel1,
                                  const float* __restrict__ wroot2,
                                  const float* __restrict__ wrel2) {
    const int total = XF4 + 2 * WF4L;
    for (int idx = blockIdx.x * blockDim.x + threadIdx.x; idx < total;
         idx += gridDim.x * blockDim.x) {
        float4 v;
        uint32_t* dst;
        if (idx < XF4) {
            const int m = idx >> 6;            // DD/4 = 64
            const int dq = idx & 63;
            v = ((const float4*)x)[idx];
            dst = g_acat + (size_t)m * K_TOTAL + dq * 4;
        } else {
            const int j = idx - XF4;
            const int L = j / WF4L;
            const int j2 = j - L * WF4L;
            const float4* src = (j2 < ROOTF4)
                ? ((const float4*)(L ? wroot2 : wroot1)) + j2
                : ((const float4*)(L ? wrel2 : wrel1)) + (j2 - ROOTF4);
            v = *src;
            dst = g_w + (size_t)L * W_L + (size_t)j2 * 4;
        }
        uint4 u;
        u.x = f2tf32(v.x); u.y = f2tf32(v.y);
        u.z = f2tf32(v.z); u.w = f2tf32(v.w);
        *(uint4*)dst = u;
    }
}

// ---------------------------------------------------------------------------
// Kernel 4: sparse mean-aggregation via compact lists; writes tf32 directly
// into g_acat[layer] segments 1 and 2. Block = (j, b), 64 threads.
// Unrolled x4 with packed index loads and dual accumulators for MLP.
// ---------------------------------------------------------------------------
__global__ void __launch_bounds__(64)
aggregate_kernel(const float* __restrict__ x, int layer) {
    const int j = blockIdx.x;
    const int b = blockIdx.y;
    const int t = threadIdx.x;   // 0..63
    const size_t o = (size_t)b * NN + j;

    __shared__ alignas(8) unsigned short slist[NN];
    __shared__ int sn0, sn1;
    __shared__ float si0, si1;
    if (t == 0) {
        sn0 = g_cnt[0][o]; sn1 = g_cnt[1][o];
        si0 = g_inv[0][o]; si1 = g_inv[1][o];
    }
    const unsigned short* __restrict__ lst = g_list + o * NN;
    #pragma unroll
    for (int k = 0; k < NN / 2 / 64; k++)
        ((unsigned int*)slist)[t + k * 64] = ((const unsigned int*)lst)[t + k * 64];
    __syncthreads();

    const int n0 = sn0, n1 = sn1;
    const float inv0 = si0, inv1 = si1;
    const float4* __restrict__ xb = (const float4*)(
        (layer ? (const float*)g_h : x) + (size_t)b * NN * DD);

    // relation 0: forward list, packed uint2 index loads, 2 accumulators
    float4 p0 = make_float4(0.f, 0.f, 0.f, 0.f);
    float4 p1 = make_float4(0.f, 0.f, 0.f, 0.f);
    int k = 0;
    for (; k + 4 <= n0; k += 4) {
        const uint32_t w0 = *(const uint32_t*)&slist[k];
        const uint32_t w1 = *(const uint32_t*)&slist[k + 2];
        const float4 v0 = xb[(w0 & 0xffffu) * (DD / 4) + t];
        const float4 v1 = xb[(w0 >> 16)     * (DD / 4) + t];
        const float4 v2 = xb[(w1 & 0xffffu) * (DD / 4) + t];
        const float4 v3 = xb[(w1 >> 16)     * (DD / 4) + t];
        p0.x += v0.x + v2.x; p0.y += v0.y + v2.y;
        p0.z += v0.z + v2.z; p0.w += v0.w + v2.w;
        p1.x += v1.x + v3.x; p1.y += v1.y + v3.y;
        p1.z += v1.z + v3.z; p1.w += v1.w + v3.w;
    }
    for (; k < n0; k++) {
        const float4 v = xb[slist[k] * (DD / 4) + t];
        p0.x += v.x; p0.y += v.y; p0.z += v.z; p0.w += v.w;
    }
    float4 a0 = make_float4(p0.x + p1.x, p0.y + p1.y, p0.z + p1.z, p0.w + p1.w);

    // relation 1: backward list, scalar index loads, 2 accumulators
    float4 q0 = make_float4(0.f, 0.f, 0.f, 0.f);
    float4 q1 = make_float4(0.f, 0.f, 0.f, 0.f);
    k = 0;
    for (; k + 4 <= n1; k += 4) {
        const int i0 = slist[NN - 1 - k];
        const int i1 = slist[NN - 2 - k];
        const int i2 = slist[NN - 3 - k];
        const int i3 = slist[NN - 4 - k];
        const float4 v0 = xb[i0 * (DD / 4) + t];
        const float4 v1 = xb[i1 * (DD / 4) + t];
        const float4 v2 = xb[i2 * (DD / 4) + t];
        const float4 v3 = xb[i3 * (DD / 4) + t];
        q0.x += v0.x + v2.x; q0.y += v0.y + v2.y;
        q0.z += v0.z + v2.z; q0.w += v0.w + v2.w;
        q1.x += v1.x + v3.x; q1.y += v1.y + v3.y;
        q1.z += v1.z + v3.z; q1.w += v1.w + v3.w;
    }
    for (; k < n1; k++) {
        const float4 v = xb[slist[NN - 1 - k] * (DD / 4) + t];
        q0.x += v.x; q0.y += v.y; q0.z += v.z; q0.w += v.w;
    }
    float4 a1 = make_float4(q0.x + q1.x, q0.y + q1.y, q0.z + q1.z, q0.w + q1.w);

    uint32_t* __restrict__ base =
        g_acat + (size_t)layer * ACAT_L + o * K_TOTAL;
    uint4 u0, u1;
    u0.x = f2tf32(a0.x * inv0); u0.y = f2tf32(a0.y * inv0);
    u0.z = f2tf32(a0.z * inv0); u0.w = f2tf32(a0.w * inv0);
    u1.x = f2tf32(a1.x * inv1); u1.y = f2tf32(a1.y * inv1);
    u1.z = f2tf32(a1.z * inv1); u1.w = f2tf32(a1.w * inv1);
    ((uint4*)(base + DD))[t]     = u0;   // seg1
    ((uint4*)(base + 2 * DD))[t] = u1;   // seg2
}

// ---------------------------------------------------------------------------
// Kernel 5: TF32 tensor-core GEMM + bias + ELU, cp.async 3-stage pipeline.
//   out[m,e] = elu( Acat[m,:] @ W[:,e] + bias[e] )
// M=8192, K=768, N=256. Block tile 64x128, 4 warps (2M x 2N), warp 32x64.
// ---------------------------------------------------------------------------
__device__ __forceinline__ void mma_tf32(float c[4], const uint32_t a[4],
                                         uint32_t b0, uint32_t b1) {
    asm volatile(
        "mma.sync.aligned.m16n8k8.row.col.f32.tf32.tf32.f32 "
        "{%0,%1,%2,%3}, {%4,%5,%6,%7}, {%8,%9}, {%0,%1,%2,%3};"
        : "+f"(c[0]), "+f"(c[1]), "+f"(c[2]), "+f"(c[3])
        : "r"(a[0]), "r"(a[1]), "r"(a[2]), "r"(a[3]), "r"(b0), "r"(b1));
}

__device__ __forceinline__ void cp16(uint32_t dst, const void* src) {
    asm volatile("cp.async.cg.shared.global [%0], [%1], 16;"
                 :: "r"(dst), "l"(src));
}

#define ASTR 20    // A shared stride (floats): [m][k], conflict-free fragments
#define BSTR 132   // B shared stride (floats): [k][n], conflict-free fragments

__global__ void __launch_bounds__(128)
rgcn_gemm_kernel(int layer, const float* __restrict__ bias,
                 float* __restrict__ dout) {
    __shared__ uint32_t As[STG][64][ASTR];    // [stage][m][k]
    __shared__ uint32_t Bs[STG][BKT][BSTR];   // [stage][k][n]

    const uint32_t* __restrict__ Ag = g_acat + (size_t)layer * ACAT_L;
    const uint32_t* __restrict__ Bg = g_w + (size_t)layer * W_L;

    const int t    = threadIdx.x;
    const int lane = t & 31;
    const int wid  = t >> 5;
    const int wm   = wid & 1;          // warp M index (0..1)
    const int wn   = wid >> 1;         // warp N index (0..1)
    const int gid  = lane >> 2;        // 0..7
    const int tig  = lane & 3;         // 0..3
    const int m0   = blockIdx.y * 64;
    const int e0   = blockIdx.x * 128;

    const uint32_t asb = (uint32_t)__cvta_generic_to_shared(As);
    const uint32_t bsb = (uint32_t)__cvta_generic_to_shared(Bs);

    // copy mappings
    const int ar0 = t >> 2;            // A chunk 0: row 0..31
    const int ako = (t & 3) << 2;      // k offset 0/4/8/12
    const int br0 = t >> 5;            // B chunk i: row = br0 + 4*i
    const int bno = (t & 31) << 2;     // n offset

    auto issue_tile = [&](int tile) {
        if (tile < NT) {
            const int stage = tile % STG;
            const int kg = tile * BKT;
            #pragma unroll
            for (int i = 0; i < 2; i++) {
                const int r = ar0 + 32 * i;
                cp16(asb + (uint32_t)(((stage * 64 + r) * ASTR + ako) * 4),
                     Ag + (size_t)(m0 + r) * K_TOTAL + kg + ako);
            }
            #pragma unroll
            for (int i = 0; i < 4; i++) {
                const int r = br0 + 4 * i;
                cp16(bsb + (uint32_t)(((stage * BKT + r) * BSTR + bno) * 4),
                     Bg + (size_t)(kg + r) * DD + e0 + bno);
            }
        }
        asm volatile("cp.async.commit_group;");
    };

    // prologue: tiles 0 .. STG-2
    issue_tile(0);
    issue_tile(1);

    float acc[2][8][4] = {};

    for (int kt = 0; kt < NT; kt++) {
        asm volatile("cp.async.wait_group %0;" :: "n"(STG - 2));
        __syncthreads();

        issue_tile(kt + STG - 1);

        const int st = kt % STG;
        #pragma unroll
        for (int ks = 0; ks < 2; ks++) {
            const int kb = ks * 8;
            uint32_t af[2][4];
            #pragma unroll
            for (int mt = 0; mt < 2; mt++) {
                const int m = wm * 32 + mt * 16 + gid;
                af[mt][0] = As[st][m][kb + tig];
                af[mt][1] = As[st][m + 8][kb + tig];
                af[mt][2] = As[st][m][kb + tig + 4];
                af[mt][3] = As[st][m + 8][kb + tig + 4];
            }
            #pragma unroll
            for (int nt = 0; nt < 8; nt++) {
                const int n = wn * 64 + nt * 8 + gid;
                const uint32_t b0 = Bs[st][kb + tig][n];
                const uint32_t b1 = Bs[st][kb + tig + 4][n];
                mma_tf32(acc[0][nt], af[0], b0, b1);
                mma_tf32(acc[1][nt], af[1], b0, b1);
            }
        }
    }

    // epilogue: bias + ELU
    float* __restrict__ outf = (layer == 0) ? (float*)g_h : dout;
    uint32_t* __restrict__ outt = g_acat + ACAT_L;   // layer-1 seg0 (only used if layer==0)
    const float2* __restrict__ bias2 = (const float2*)bias;

    #pragma unroll
    for (int mt = 0; mt < 2; mt++) {
        const int mrow = m0 + wm * 32 + mt * 16 + gid;
        #pragma unroll
        for (int nt = 0; nt < 8; nt++) {
            const int col = e0 + wn * 64 + nt * 8 + 2 * tig;
            const float2 bb = bias2[col >> 1];
            float v0 = acc[mt][nt][0] + bb.x;
            float v1 = acc[mt][nt][1] + bb.y;
            float v2 = acc[mt][nt][2] + bb.x;
            float v3 = acc[mt][nt][3] + bb.y;
            v0 = (v0 > 0.f) ? v0 : expm1f(v0);
            v1 = (v1 > 0.f) ? v1 : expm1f(v1);
            v2 = (v2 > 0.f) ? v2 : expm1f(v2);
            v3 = (v3 > 0.f) ? v3 : expm1f(v3);
            *(float2*)&outf[(size_t)mrow * DD + col]       = make_float2(v0, v1);
            *(float2*)&outf[(size_t)(mrow + 8) * DD + col] = make_float2(v2, v3);
            if (layer == 0) {
                uint2 u0; u0.x = f2tf32(v0); u0.y = f2tf32(v1);
                uint2 u1; u1.x = f2tf32(v2); u1.y = f2tf32(v3);
                *(uint2*)&outt[(size_t)mrow * K_TOTAL + col]       = u0;
                *(uint2*)&outt[(size_t)(mrow + 8) * K_TOTAL + col] = u1;
            }
        }
    }
}

// ---------------------------------------------------------------------------
// Launch: masks+lists+cvt once, then per layer: agg -> TF32 GEMM+bias+ELU.
// ---------------------------------------------------------------------------
extern "C" void kernel_launch(void* const* d_in, const int* in_sizes, int n_in,
                              void* d_out, int out_size) {
    const float* x       = (const float*)d_in[0];
    const float* w_rel1  = (const float*)d_in[1];
    const float* w_root1 = (const float*)d_in[2];
    const float* b1      = (const float*)d_in[3];
    const float* w_rel2  = (const float*)d_in[4];
    const float* w_root2 = (const float*)d_in[5];
    const float* b2      = (const float*)d_in[6];
    const int* aug   = (const int*)d_in[7];
    const int* punct = (const int*)d_in[8];
    float* out = (float*)d_out;

    build_masks_kernel<<<dim3(NN / 32, NN / 32, BS), dim3(32, 8)>>>(aug, punct);
    build_lists_kernel<<<dim3(NN, BS), 32>>>();
    cvt_inputs_kernel<<<1184, 256>>>(x, w_root1, w_rel1, w_root2, w_rel2);

    // Layer 1: agg(x) -> acat0 seg1/2; gemm -> g_h + acat1 seg0
    aggregate_kernel<<<dim3(NN, BS), 64>>>(x, 0);
    rgcn_gemm_kernel<<<dim3(DD / 128, M_TOTAL / 64), 128>>>(0, b1, nullptr);

    // Layer 2: agg(h) -> acat1 seg1/2; gemm -> out
    aggregate_kernel<<<dim3(NN, BS), 64>>>(nullptr, 1);
    rgcn_gemm_kernel<<<dim3(DD / 128, M_TOTAL / 64), 128>>>(1, b2, out);
}